// round 9
// baseline (speedup 1.0000x reference)
#include <cuda_runtime.h>
#include <cstdint>

#define B_ 16
#define T_ 2048
#define D_ 256
#define C_ 8
#define TILE 32
#define NCHUNKS (T_ / TILE)      // 64
#define NBLOCKS (B_ * NCHUNKS)   // 1024
#define NTHREADS 128

typedef unsigned long long ull;
union f4u { float4 v; ull u[2]; };

__device__ __forceinline__ ull ffma2(ull a, ull b, ull c) {
    ull d;
    asm("fma.rn.f32x2 %0, %1, %2, %3;" : "=l"(d) : "l"(a), "l"(b), "l"(c));
    return d;
}
__device__ __forceinline__ float2 upk(ull v) {
    float2 r;
    asm("mov.b64 {%0, %1}, %2;" : "=f"(r.x), "=f"(r.y) : "l"(v));
    return r;
}
__device__ __forceinline__ ull pk2(float lo, float hi) {
    ull r;
    asm("mov.b64 %0, {%1, %2};" : "=l"(r) : "f"(lo), "f"(hi));
    return r;
}
__device__ __forceinline__ void cp16(uint32_t saddr, const void* g) {
    asm volatile("cp.async.cg.shared.global [%0], [%1], 16;" :: "r"(saddr), "l"(g));
}
#define CP_COMMIT() asm volatile("cp.async.commit_group;")
#define CP_WAIT0()  asm volatile("cp.async.wait_group 0;")

__global__ void lde_zero_kernel(float* __restrict__ out, int n) {
    int i = blockIdx.x * blockDim.x + threadIdx.x;
    if (i < n) out[i] = 0.0f;
}

__global__ void __launch_bounds__(NTHREADS, 5) lde_main_kernel(
    const float* __restrict__ x,        // (B,T,D)
    const float* __restrict__ centers,  // (C,D)
    const float* __restrict__ scale,    // (C,)
    float* __restrict__ out)            // (B, C*D)
{
    __shared__ float4 xbuf[TILE * 64];   // 32 KB, swizzled slot = d4 ^ t
    __shared__ float4 ct[64 * C_];       // 8 KB: [d4][c]
    __shared__ float  a_s[TILE * C_];    // softmax weights
    __shared__ float  asum_s[C_];
    __shared__ float  csq_s[C_];
    __shared__ float  scl_s[C_];

    const int tid  = threadIdx.x;
    const int w    = tid >> 5;           // 0..3
    const int lane = tid & 31;
    const int b     = blockIdx.x >> 6;        // / NCHUNKS
    const int chunk = blockIdx.x & (NCHUNKS - 1);

    // ---- 1) kick off x tile load (32 KB), 16 cp.async per thread ----
    const float4* gx4 = (const float4*)(x + ((size_t)b * T_ + chunk * TILE) * D_);
    const uint32_t xs_base = (uint32_t)__cvta_generic_to_shared(xbuf);
#pragma unroll
    for (int j = 0; j < 16; j++) {
        int i = tid + j * NTHREADS;           // 0..2047
        int t = i >> 6, d4 = i & 63;
        cp16(xs_base + (uint32_t)((t * 64 + (d4 ^ t)) * 16), gx4 + i);
    }
    CP_COMMIT();

    // ---- 2) init (overlaps cp.async flight) ----
    if (tid < C_) { asum_s[tid] = 0.0f; scl_s[tid] = scale[tid]; }
    for (int i = tid; i < C_ * D_; i += NTHREADS) {
        int c = i >> 8, d = i & 255;
        ((float*)ct)[((d >> 2) * C_ + c) * 4 + (d & 3)] = centers[i];
    }
    // csq: warp w handles clusters 2w and 2w+1 (from global, overlaps cp.async)
    {
        float s0 = 0.0f, s1 = 0.0f;
#pragma unroll
        for (int j = 0; j < 8; j++) {
            float v0 = centers[(2 * w) * D_ + lane + 32 * j];
            float v1 = centers[(2 * w + 1) * D_ + lane + 32 * j];
            s0 = fmaf(v0, v0, s0);
            s1 = fmaf(v1, v1, s1);
        }
#pragma unroll
        for (int o = 16; o; o >>= 1) {
            s0 += __shfl_xor_sync(0xffffffffu, s0, o);
            s1 += __shfl_xor_sync(0xffffffffu, s1, o);
        }
        if (lane == 0) { csq_s[2 * w] = s0; csq_s[2 * w + 1] = s1; }
    }

    CP_WAIT0();
    __syncthreads();   // barrier #1

    // ---- 3) phase A + softmax, fully warp-local ----
    // warp w owns tokens [8w, 8w+8); lane = (dpart = lane>>3) x (tok = lane&7)
    {
        const int tok   = lane & 7;
        const int dpart = lane >> 3;
        const int t     = w * 8 + tok;

        ull red[9];
#pragma unroll
        for (int j = 0; j < 9; j++) red[j] = 0ULL;
#pragma unroll
        for (int i = 0; i < 16; i++) {
            const int d4 = dpart * 16 + i;
            f4u xv; xv.v = xbuf[t * 64 + (d4 ^ t)];
#pragma unroll
            for (int c = 0; c < C_; c++) {
                f4u cv; cv.v = ct[d4 * C_ + c];
                red[c] = ffma2(xv.u[0], cv.u[0], ffma2(xv.u[1], cv.u[1], red[c]));
            }
            red[8] = ffma2(xv.u[0], xv.u[0], ffma2(xv.u[1], xv.u[1], red[8]));
        }

        // collapse pairs + butterfly over dpart (xor 8, xor 16)
        float rf[9];
#pragma unroll
        for (int j = 0; j < 9; j++) {
            float2 p = upk(red[j]);
            float v = p.x + p.y;
            v += __shfl_xor_sync(0xffffffffu, v, 8);
            v += __shfl_xor_sync(0xffffffffu, v, 16);
            rf[j] = v;
        }
        // every lane now holds complete dots for token t; lane covers clusters
        // c0 = 2*dpart, c1 = 2*dpart+1
        const int c0 = 2 * dpart, c1 = 2 * dpart + 1;
        const float xsq = rf[8];
        float lg0 = scl_s[c0] * (2.0f * rf[c0] - xsq - csq_s[c0]);
        float lg1 = scl_s[c1] * (2.0f * rf[c1] - xsq - csq_s[c1]);
        float m = fmaxf(lg0, lg1);
        m = fmaxf(m, __shfl_xor_sync(0xffffffffu, m, 8));
        m = fmaxf(m, __shfl_xor_sync(0xffffffffu, m, 16));
        const float e0 = __expf(lg0 - m);
        const float e1 = __expf(lg1 - m);
        float sd = e0 + e1;
        sd += __shfl_xor_sync(0xffffffffu, sd, 8);
        sd += __shfl_xor_sync(0xffffffffu, sd, 16);
        const float inv = 1.0f / sd;
        const float a0 = e0 * inv, a1 = e1 * inv;
        *(float2*)&a_s[t * 8 + c0] = make_float2(a0, a1);   // one STS.64

        // asum: reduce over the 8 tokens of this warp (xor 1,2,4)
        float r0 = a0, r1 = a1;
#pragma unroll
        for (int o = 1; o < 8; o <<= 1) {
            r0 += __shfl_xor_sync(0xffffffffu, r0, o);
            r1 += __shfl_xor_sync(0xffffffffu, r1, o);
        }
        if (tok == 0) {
            atomicAdd(&asum_s[c0], r0);   // 8 tiny atomics per block total
            atomicAdd(&asum_s[c1], r1);
        }
    }
    __syncthreads();   // barrier #2

    // ---- 4) phase B: thread tid owns dims {2*tid, 2*tid+1}, all 32 tokens ----
    const int d4l = tid >> 1;            // float4 slot of this thread's dims
    const int off = (tid & 1) * 2;       // word offset within the float4

    ull acc2[8];                         // acc2[j*2+dd] = (acc[2j][d_dd], acc[2j+1][d_dd])
#pragma unroll
    for (int j = 0; j < 8; j++) acc2[j] = 0ULL;
    {
        const float* xbf = (const float*)xbuf;
#pragma unroll 4
        for (int t = 0; t < TILE; t++) {
            const ull xp = *(const ull*)(xbf + (t * 64 + (d4l ^ t)) * 4 + off);
            const float2 xv = upk(xp);
            const ull xd0 = pk2(xv.x, xv.x);
            const ull xd1 = pk2(xv.y, xv.y);
            f4u a0; a0.v = *(const float4*)&a_s[t * 8];      // (a0,a1),(a2,a3)
            f4u a1; a1.v = *(const float4*)&a_s[t * 8 + 4];  // (a4,a5),(a6,a7)
            acc2[0] = ffma2(a0.u[0], xd0, acc2[0]);
            acc2[1] = ffma2(a0.u[0], xd1, acc2[1]);
            acc2[2] = ffma2(a0.u[1], xd0, acc2[2]);
            acc2[3] = ffma2(a0.u[1], xd1, acc2[3]);
            acc2[4] = ffma2(a1.u[0], xd0, acc2[4]);
            acc2[5] = ffma2(a1.u[0], xd1, acc2[5]);
            acc2[6] = ffma2(a1.u[1], xd0, acc2[6]);
            acc2[7] = ffma2(a1.u[1], xd1, acc2[7]);
        }
    }

    // ---- 5) epilogue: atomic accumulate into out ----
    {
        const float* ctf = (const float*)ct;
        float* ob = out + b * (C_ * D_);
        float as[C_];
#pragma unroll
        for (int c = 0; c < C_; c++) as[c] = asum_s[c];
        const int d0 = 2 * tid, d1 = 2 * tid + 1;
#pragma unroll
        for (int j = 0; j < 4; j++) {
            const int c0 = 2 * j, c1 = 2 * j + 1;
            const float2 p0 = upk(acc2[j * 2]);      // (acc[c0][d0], acc[c1][d0])
            const float2 p1 = upk(acc2[j * 2 + 1]);  // (acc[c0][d1], acc[c1][d1])
            const float cv00 = ctf[(d4l * C_ + c0) * 4 + off];
            const float cv01 = ctf[(d4l * C_ + c0) * 4 + off + 1];
            const float cv10 = ctf[(d4l * C_ + c1) * 4 + off];
            const float cv11 = ctf[(d4l * C_ + c1) * 4 + off + 1];
            atomicAdd(ob + c0 * 256 + d0, p0.x - as[c0] * cv00);
            atomicAdd(ob + c0 * 256 + d1, p1.x - as[c0] * cv01);
            atomicAdd(ob + c1 * 256 + d0, p0.y - as[c1] * cv10);
            atomicAdd(ob + c1 * 256 + d1, p1.y - as[c1] * cv11);
        }
    }
}

extern "C" void kernel_launch(void* const* d_in, const int* in_sizes, int n_in,
                              void* d_out, int out_size) {
    const float* x       = (const float*)d_in[0];
    const float* centers = (const float*)d_in[1];
    const float* scale   = (const float*)d_in[2];
    float* out           = (float*)d_out;
    (void)in_sizes; (void)n_in;

    lde_zero_kernel<<<(out_size + 255) / 256, 256>>>(out, out_size);
    lde_main_kernel<<<NBLOCKS, NTHREADS>>>(x, centers, scale, out);
}

// round 10
// speedup vs baseline: 1.0012x; 1.0012x over previous
#include <cuda_runtime.h>
#include <cstdint>

#define B_ 16
#define T_ 2048
#define D_ 256
#define C_ 8
#define TILE 32
#define NCHUNKS (T_ / TILE)      // 64
#define NBLOCKS (B_ * NCHUNKS)   // 1024
#define NTHREADS 128

typedef unsigned long long ull;
union f4u { float4 v; ull u[2]; };

// scratch: per-block partial aggregates, layout [block][d][c] (d=0..255, c=0..7)
__device__ float g_scratch[NBLOCKS * 2048];
__device__ float g_asum[NBLOCKS * C_];

__device__ __forceinline__ ull ffma2(ull a, ull b, ull c) {
    ull d;
    asm("fma.rn.f32x2 %0, %1, %2, %3;" : "=l"(d) : "l"(a), "l"(b), "l"(c));
    return d;
}
__device__ __forceinline__ float2 upk(ull v) {
    float2 r;
    asm("mov.b64 {%0, %1}, %2;" : "=f"(r.x), "=f"(r.y) : "l"(v));
    return r;
}
__device__ __forceinline__ ull pk2(float lo, float hi) {
    ull r;
    asm("mov.b64 %0, {%1, %2};" : "=l"(r) : "f"(lo), "f"(hi));
    return r;
}
__device__ __forceinline__ void cp16(uint32_t saddr, const void* g) {
    asm volatile("cp.async.cg.shared.global [%0], [%1], 16;" :: "r"(saddr), "l"(g));
}
#define CP_COMMIT() asm volatile("cp.async.commit_group;")
#define CP_WAIT0()  asm volatile("cp.async.wait_group 0;")

__global__ void __launch_bounds__(NTHREADS, 5) lde_main_kernel(
    const float* __restrict__ x,        // (B,T,D)
    const float* __restrict__ centers,  // (C,D)
    const float* __restrict__ scale)    // (C,)
{
    __shared__ float4 xbuf[TILE * 64];   // 32 KB, swizzled slot = d4 ^ t
    __shared__ float4 ct[64 * C_];       // 8 KB: [d4][c]
    __shared__ float  logit[TILE * 9];   // per token: 8 dots + xsq
    __shared__ float  a_s[TILE * C_];    // softmax weights
    __shared__ float  asum_s[C_];
    __shared__ float  csq_s[C_];
    __shared__ float  scl_s[C_];

    const int tid  = threadIdx.x;
    const int w    = tid >> 5;           // 0..3
    const int lane = tid & 31;
    const int b     = blockIdx.x >> 6;        // / NCHUNKS
    const int chunk = blockIdx.x & (NCHUNKS - 1);

    // ---- 1) kick off x tile load (32 KB), 16 cp.async per thread ----
    const float4* gx4 = (const float4*)(x + ((size_t)b * T_ + chunk * TILE) * D_);
    const uint32_t xs_base = (uint32_t)__cvta_generic_to_shared(xbuf);
#pragma unroll
    for (int j = 0; j < 16; j++) {
        int i = tid + j * NTHREADS;           // 0..2047
        int t = i >> 6, d4 = i & 63;
        cp16(xs_base + (uint32_t)((t * 64 + (d4 ^ t)) * 16), gx4 + i);
    }
    CP_COMMIT();

    // ---- 2) init (overlaps cp.async flight) ----
    for (int i = tid; i < TILE * 9; i += NTHREADS) logit[i] = 0.0f;
    if (tid < C_) { asum_s[tid] = 0.0f; scl_s[tid] = scale[tid]; }
    for (int i = tid; i < C_ * D_; i += NTHREADS) {
        int c = i >> 8, d = i & 255;
        ((float*)ct)[((d >> 2) * C_ + c) * 4 + (d & 3)] = centers[i];
    }
    // csq: warp w handles clusters 2w and 2w+1
    {
        float s0 = 0.0f, s1 = 0.0f;
#pragma unroll
        for (int j = 0; j < 8; j++) {
            float v0 = centers[(2 * w) * D_ + lane + 32 * j];
            float v1 = centers[(2 * w + 1) * D_ + lane + 32 * j];
            s0 = fmaf(v0, v0, s0);
            s1 = fmaf(v1, v1, s1);
        }
#pragma unroll
        for (int o = 16; o; o >>= 1) {
            s0 += __shfl_xor_sync(0xffffffffu, s0, o);
            s1 += __shfl_xor_sync(0xffffffffu, s1, o);
        }
        if (lane == 0) { csq_s[2 * w] = s0; csq_s[2 * w + 1] = s1; }
    }

    CP_WAIT0();
    __syncthreads();   // barrier #1

    // ---- 3) phase A: lane = token, warp w covers d4 in [16w, 16w+16) ----
    {
        ull red[9];
#pragma unroll
        for (int j = 0; j < 9; j++) red[j] = 0ULL;
#pragma unroll
        for (int i = 0; i < 16; i++) {
            const int d4 = w * 16 + i;
            f4u xv; xv.v = xbuf[lane * 64 + (d4 ^ lane)];
#pragma unroll
            for (int c = 0; c < C_; c++) {
                f4u cv; cv.v = ct[d4 * C_ + c];
                red[c] = ffma2(xv.u[0], cv.u[0], ffma2(xv.u[1], cv.u[1], red[c]));
            }
            red[8] = ffma2(xv.u[0], xv.u[0], ffma2(xv.u[1], xv.u[1], red[8]));
        }
#pragma unroll
        for (int j = 0; j < 9; j++) {
            float2 p = upk(red[j]);
            atomicAdd(&logit[lane * 9 + j], p.x + p.y);   // 4-way combine
        }
    }
    __syncthreads();   // barrier #2

    // ---- 4) softmax: thread = (t = tid/4, cluster pair q = tid%4) ----
    {
        const int t  = tid >> 2;
        const int q  = tid & 3;
        const int c0 = 2 * q, c1 = 2 * q + 1;
        const float dot0 = logit[t * 9 + c0];
        const float dot1 = logit[t * 9 + c1];
        const float xsq  = logit[t * 9 + 8];
        float lg0 = scl_s[c0] * (2.0f * dot0 - xsq - csq_s[c0]);
        float lg1 = scl_s[c1] * (2.0f * dot1 - xsq - csq_s[c1]);
        float m = fmaxf(lg0, lg1);
        m = fmaxf(m, __shfl_xor_sync(0xffffffffu, m, 1));
        m = fmaxf(m, __shfl_xor_sync(0xffffffffu, m, 2));
        const float e0 = __expf(lg0 - m);
        const float e1 = __expf(lg1 - m);
        float sd = e0 + e1;
        sd += __shfl_xor_sync(0xffffffffu, sd, 1);
        sd += __shfl_xor_sync(0xffffffffu, sd, 2);
        const float inv = 1.0f / sd;
        const float a0 = e0 * inv, a1 = e1 * inv;
        *(float2*)&a_s[t * 8 + c0] = make_float2(a0, a1);   // STS.64
        float r0 = a0, r1 = a1;
        r0 += __shfl_xor_sync(0xffffffffu, r0, 4);
        r1 += __shfl_xor_sync(0xffffffffu, r1, 4);
        r0 += __shfl_xor_sync(0xffffffffu, r0, 8);
        r1 += __shfl_xor_sync(0xffffffffu, r1, 8);
        r0 += __shfl_xor_sync(0xffffffffu, r0, 16);
        r1 += __shfl_xor_sync(0xffffffffu, r1, 16);
        if (lane < 4) {
            atomicAdd(&asum_s[c0], r0);
            atomicAdd(&asum_s[c1], r1);
        }
    }
    __syncthreads();   // barrier #3

    // ---- 5) phase B: thread tid owns dims {2*tid, 2*tid+1}, all 32 tokens ----
    const int d4l = tid >> 1;
    const int off = (tid & 1) * 2;

    ull acc2[8];   // acc2[j*2+dd] = (acc[2j][d_dd], acc[2j+1][d_dd])
#pragma unroll
    for (int j = 0; j < 8; j++) acc2[j] = 0ULL;
    {
        const float* xbf = (const float*)xbuf;
#pragma unroll 4
        for (int t = 0; t < TILE; t++) {
            const ull xp = *(const ull*)(xbf + (t * 64 + (d4l ^ t)) * 4 + off);
            const float2 xv = upk(xp);
            const ull xd0 = pk2(xv.x, xv.x);
            const ull xd1 = pk2(xv.y, xv.y);
            f4u a0; a0.v = *(const float4*)&a_s[t * 8];
            f4u a1; a1.v = *(const float4*)&a_s[t * 8 + 4];
            acc2[0] = ffma2(a0.u[0], xd0, acc2[0]);
            acc2[1] = ffma2(a0.u[0], xd1, acc2[1]);
            acc2[2] = ffma2(a0.u[1], xd0, acc2[2]);
            acc2[3] = ffma2(a0.u[1], xd1, acc2[3]);
            acc2[4] = ffma2(a1.u[0], xd0, acc2[4]);
            acc2[5] = ffma2(a1.u[0], xd1, acc2[5]);
            acc2[6] = ffma2(a1.u[1], xd0, acc2[6]);
            acc2[7] = ffma2(a1.u[1], xd1, acc2[7]);
        }
    }

    // ---- 6) epilogue: plain vectorized stores of raw partials ----
    {
        float* sb = g_scratch + (size_t)blockIdx.x * 2048;   // [d][c]
        const int d0 = 2 * tid, d1 = 2 * tid + 1;
        f4u q0, q1, q2, q3;
        q0.u[0] = acc2[0]; q0.u[1] = acc2[2];   // row d0, c0..3
        q1.u[0] = acc2[4]; q1.u[1] = acc2[6];   // row d0, c4..7
        q2.u[0] = acc2[1]; q2.u[1] = acc2[3];   // row d1, c0..3
        q3.u[0] = acc2[5]; q3.u[1] = acc2[7];   // row d1, c4..7
        *(float4*)(sb + d0 * 8)     = q0.v;
        *(float4*)(sb + d0 * 8 + 4) = q1.v;
        *(float4*)(sb + d1 * 8)     = q2.v;
        *(float4*)(sb + d1 * 8 + 4) = q3.v;
        if (tid < C_) g_asum[blockIdx.x * C_ + tid] = asum_s[tid];
    }
}

// stage 2: out[b][c][d] = sum_k scratch[b*64+k][d][c] - (sum_k asum)*centers[c][d]
__global__ void __launch_bounds__(256) lde_reduce_kernel(
    const float* __restrict__ centers,
    float* __restrict__ out)
{
    const int b    = blockIdx.x;          // 16
    const int dq   = blockIdx.y;          // 4
    const int kseg = threadIdx.x >> 6;    // 0..3
    const int dl   = threadIdx.x & 63;
    const int d    = dq * 64 + dl;

    __shared__ float red[4][64][9];       // padded, conflict-free scalar stores
    __shared__ float asumtot[C_];

    if (threadIdx.x < C_) {
        float s = 0.0f;
#pragma unroll
        for (int k = 0; k < 64; k++)
            s += g_asum[(b * 64 + k) * C_ + threadIdx.x];
        asumtot[threadIdx.x] = s;
    }

    float acc[C_];
#pragma unroll
    for (int c = 0; c < C_; c++) acc[c] = 0.0f;

    const float* base = g_scratch + ((size_t)b * 64 + kseg * 16) * 2048 + d * 8;
#pragma unroll 4
    for (int k = 0; k < 16; k++) {
        float4 p0 = *(const float4*)(base + (size_t)k * 2048);
        float4 p1 = *(const float4*)(base + (size_t)k * 2048 + 4);
        acc[0] += p0.x; acc[1] += p0.y; acc[2] += p0.z; acc[3] += p0.w;
        acc[4] += p1.x; acc[5] += p1.y; acc[6] += p1.z; acc[7] += p1.w;
    }
#pragma unroll
    for (int c = 0; c < C_; c++) red[kseg][dl][c] = acc[c];
    __syncthreads();

    if (kseg == 0) {
#pragma unroll
        for (int s = 1; s < 4; s++)
#pragma unroll
            for (int c = 0; c < C_; c++) acc[c] += red[s][dl][c];
        float* ob = out + b * (C_ * D_);
#pragma unroll
        for (int c = 0; c < C_; c++)
            ob[c * 256 + d] = acc[c] - asumtot[c] * centers[c * 256 + d];
    }
}

extern "C" void kernel_launch(void* const* d_in, const int* in_sizes, int n_in,
                              void* d_out, int out_size) {
    const float* x       = (const float*)d_in[0];
    const float* centers = (const float*)d_in[1];
    const float* scale   = (const float*)d_in[2];
    float* out           = (float*)d_out;
    (void)in_sizes; (void)n_in; (void)out_size;

    lde_main_kernel<<<NBLOCKS, NTHREADS>>>(x, centers, scale);
    lde_reduce_kernel<<<dim3(B_, 4), 256>>>(centers, out);
}

// round 12
// speedup vs baseline: 1.0830x; 1.0817x over previous
#include <cuda_runtime.h>
#include <cstdint>

#define B_ 16
#define T_ 2048
#define D_ 256
#define C_ 8
#define TILE 32
#define NCHUNKS (T_ / TILE)      // 64
#define NBLOCKS (B_ * NCHUNKS)   // 1024
#define NTHREADS 128

typedef unsigned long long ull;
union f4u { float4 v; ull u[2]; };

// scratch: per-block partial aggregates, layout [block][d][c] (d=0..255, c=0..7)
__device__ float g_scratch[NBLOCKS * 2048];
__device__ float g_asum[NBLOCKS * C_];

__device__ __forceinline__ ull ffma2(ull a, ull b, ull c) {
    ull d;
    asm("fma.rn.f32x2 %0, %1, %2, %3;" : "=l"(d) : "l"(a), "l"(b), "l"(c));
    return d;
}
__device__ __forceinline__ float2 upk(ull v) {
    float2 r;
    asm("mov.b64 {%0, %1}, %2;" : "=f"(r.x), "=f"(r.y) : "l"(v));
    return r;
}
__device__ __forceinline__ ull pk2(float lo, float hi) {
    ull r;
    asm("mov.b64 %0, {%1, %2};" : "=l"(r) : "f"(lo), "f"(hi));
    return r;
}
__device__ __forceinline__ void cp16(uint32_t saddr, const void* g) {
    asm volatile("cp.async.cg.shared.global [%0], [%1], 16;" :: "r"(saddr), "l"(g));
}
#define CP_COMMIT() asm volatile("cp.async.commit_group;")
#define CP_WAIT0()  asm volatile("cp.async.wait_group 0;")

__global__ void __launch_bounds__(NTHREADS, 5) lde_main_kernel(
    const float* __restrict__ x,        // (B,T,D)
    const float* __restrict__ centers,  // (C,D)
    const float* __restrict__ scale)    // (C,)
{
    __shared__ float4 xbuf[TILE * 64];   // 32 KB, swizzled slot = d4 ^ t
    __shared__ float4 ct[64 * C_];       // 8 KB: [d4][c]
    __shared__ float  logit[TILE * 9];   // per token: 8 dots + xsq
    __shared__ float  a_s[TILE * C_];    // softmax weights
    __shared__ float  asum_s[C_];
    __shared__ float  csq_s[C_];
    __shared__ float  scl_s[C_];

    const int tid  = threadIdx.x;
    const int w    = tid >> 5;           // 0..3
    const int lane = tid & 31;
    const int b     = blockIdx.x >> 6;        // / NCHUNKS
    const int chunk = blockIdx.x & (NCHUNKS - 1);

    // ---- 1) kick off x tile load (32 KB), 16 cp.async per thread ----
    const float4* gx4 = (const float4*)(x + ((size_t)b * T_ + chunk * TILE) * D_);
    const uint32_t xs_base = (uint32_t)__cvta_generic_to_shared(xbuf);
#pragma unroll
    for (int j = 0; j < 16; j++) {
        int i = tid + j * NTHREADS;           // 0..2047
        int t = i >> 6, d4 = i & 63;
        cp16(xs_base + (uint32_t)((t * 64 + (d4 ^ t)) * 16), gx4 + i);
    }
    CP_COMMIT();

    // ---- 2) init (overlaps cp.async flight) ----
    for (int i = tid; i < TILE * 9; i += NTHREADS) logit[i] = 0.0f;
    if (tid < C_) { asum_s[tid] = 0.0f; scl_s[tid] = scale[tid]; }
    for (int i = tid; i < C_ * D_; i += NTHREADS) {
        int c = i >> 8, d = i & 255;
        ((float*)ct)[((d >> 2) * C_ + c) * 4 + (d & 3)] = centers[i];
    }
    // csq: warp w handles clusters 2w and 2w+1
    {
        float s0 = 0.0f, s1 = 0.0f;
#pragma unroll
        for (int j = 0; j < 8; j++) {
            float v0 = centers[(2 * w) * D_ + lane + 32 * j];
            float v1 = centers[(2 * w + 1) * D_ + lane + 32 * j];
            s0 = fmaf(v0, v0, s0);
            s1 = fmaf(v1, v1, s1);
        }
#pragma unroll
        for (int o = 16; o; o >>= 1) {
            s0 += __shfl_xor_sync(0xffffffffu, s0, o);
            s1 += __shfl_xor_sync(0xffffffffu, s1, o);
        }
        if (lane == 0) { csq_s[2 * w] = s0; csq_s[2 * w + 1] = s1; }
    }

    CP_WAIT0();
    __syncthreads();   // barrier #1

    // ---- 3) phase A: lane = token, warp w covers d4 in [16w, 16w+16) ----
    {
        ull red[9];
#pragma unroll
        for (int j = 0; j < 9; j++) red[j] = 0ULL;
#pragma unroll
        for (int i = 0; i < 16; i++) {
            const int d4 = w * 16 + i;
            f4u xv; xv.v = xbuf[lane * 64 + (d4 ^ lane)];
#pragma unroll
            for (int c = 0; c < C_; c++) {
                f4u cv; cv.v = ct[d4 * C_ + c];
                red[c] = ffma2(xv.u[0], cv.u[0], ffma2(xv.u[1], cv.u[1], red[c]));
            }
            red[8] = ffma2(xv.u[0], xv.u[0], ffma2(xv.u[1], xv.u[1], red[8]));
        }
#pragma unroll
        for (int j = 0; j < 9; j++) {
            float2 p = upk(red[j]);
            atomicAdd(&logit[lane * 9 + j], p.x + p.y);   // 4-way combine
        }
    }
    __syncthreads();   // barrier #2

    // ---- 4) softmax: thread = (t = tid/4, cluster pair q = tid%4) ----
    {
        const int t  = tid >> 2;
        const int q  = tid & 3;
        const int c0 = 2 * q, c1 = 2 * q + 1;
        const float dot0 = logit[t * 9 + c0];
        const float dot1 = logit[t * 9 + c1];
        const float xsq  = logit[t * 9 + 8];
        float lg0 = scl_s[c0] * (2.0f * dot0 - xsq - csq_s[c0]);
        float lg1 = scl_s[c1] * (2.0f * dot1 - xsq - csq_s[c1]);
        float m = fmaxf(lg0, lg1);
        m = fmaxf(m, __shfl_xor_sync(0xffffffffu, m, 1));
        m = fmaxf(m, __shfl_xor_sync(0xffffffffu, m, 2));
        const float e0 = __expf(lg0 - m);
        const float e1 = __expf(lg1 - m);
        float sd = e0 + e1;
        sd += __shfl_xor_sync(0xffffffffu, sd, 1);
        sd += __shfl_xor_sync(0xffffffffu, sd, 2);
        const float inv = 1.0f / sd;
        const float a0 = e0 * inv, a1 = e1 * inv;
        *(float2*)&a_s[t * 8 + c0] = make_float2(a0, a1);   // STS.64
        float r0 = a0, r1 = a1;
        r0 += __shfl_xor_sync(0xffffffffu, r0, 4);
        r1 += __shfl_xor_sync(0xffffffffu, r1, 4);
        r0 += __shfl_xor_sync(0xffffffffu, r0, 8);
        r1 += __shfl_xor_sync(0xffffffffu, r1, 8);
        r0 += __shfl_xor_sync(0xffffffffu, r0, 16);
        r1 += __shfl_xor_sync(0xffffffffu, r1, 16);
        if (lane < 4) {
            atomicAdd(&asum_s[c0], r0);
            atomicAdd(&asum_s[c1], r1);
        }
    }
    __syncthreads();   // barrier #3

    // ---- 5) phase B: thread tid owns dims {2*tid, 2*tid+1}, all 32 tokens ----
    const int d4l = tid >> 1;
    const int off = (tid & 1) * 2;

    ull acc2[8];   // acc2[j*2+dd] = (acc[2j][d_dd], acc[2j+1][d_dd])
#pragma unroll
    for (int j = 0; j < 8; j++) acc2[j] = 0ULL;
    {
        const float* xbf = (const float*)xbuf;
#pragma unroll 4
        for (int t = 0; t < TILE; t++) {
            const ull xp = *(const ull*)(xbf + (t * 64 + (d4l ^ t)) * 4 + off);
            const float2 xv = upk(xp);
            const ull xd0 = pk2(xv.x, xv.x);
            const ull xd1 = pk2(xv.y, xv.y);
            f4u a0; a0.v = *(const float4*)&a_s[t * 8];
            f4u a1; a1.v = *(const float4*)&a_s[t * 8 + 4];
            acc2[0] = ffma2(a0.u[0], xd0, acc2[0]);
            acc2[1] = ffma2(a0.u[0], xd1, acc2[1]);
            acc2[2] = ffma2(a0.u[1], xd0, acc2[2]);
            acc2[3] = ffma2(a0.u[1], xd1, acc2[3]);
            acc2[4] = ffma2(a1.u[0], xd0, acc2[4]);
            acc2[5] = ffma2(a1.u[0], xd1, acc2[5]);
            acc2[6] = ffma2(a1.u[1], xd0, acc2[6]);
            acc2[7] = ffma2(a1.u[1], xd1, acc2[7]);
        }
    }

    // ---- 6) epilogue: plain vectorized stores of raw partials ----
    {
        float* sb = g_scratch + (size_t)blockIdx.x * 2048;   // [d][c]
        const int d0 = 2 * tid, d1 = 2 * tid + 1;
        f4u q0, q1, q2, q3;
        q0.u[0] = acc2[0]; q0.u[1] = acc2[2];   // row d0, c0..3
        q1.u[0] = acc2[4]; q1.u[1] = acc2[6];   // row d0, c4..7
        q2.u[0] = acc2[1]; q2.u[1] = acc2[3];   // row d1, c0..3
        q3.u[0] = acc2[5]; q3.u[1] = acc2[7];   // row d1, c4..7
        *(float4*)(sb + d0 * 8)     = q0.v;
        *(float4*)(sb + d0 * 8 + 4) = q1.v;
        *(float4*)(sb + d1 * 8)     = q2.v;
        *(float4*)(sb + d1 * 8 + 4) = q3.v;
        if (tid < C_) g_asum[blockIdx.x * C_ + tid] = asum_s[tid];
    }
}

// stage 2 (v2, high-parallelism): block (b, dg) reduces 64 k-partials for a
// 16-d group. thread = (kseg = tid>>5) x (f = tid&31 float4 within group).
__global__ void __launch_bounds__(256) lde_reduce_kernel(
    const float* __restrict__ centers,
    float* __restrict__ out)
{
    const int b    = blockIdx.x;          // 16
    const int dg   = blockIdx.y;          // 16 groups of 16 d-values
    const int tid  = threadIdx.x;
    const int f    = tid & 31;            // float4 index within 128-float group
    const int kseg = tid >> 5;            // 0..7 (8 k per segment)

    __shared__ float4 red[8][32];         // 4 KB
    __shared__ float  asred[64][8];       // 2 KB
    __shared__ float  asumtot[C_];

    // ---- partial sums over this thread's 8 k-slices (coalesced, MLP=8) ----
    const float4* base = (const float4*)g_scratch
                       + ((size_t)(b * 64 + kseg * 8)) * 512 + dg * 32 + f;
    float4 acc = make_float4(0.f, 0.f, 0.f, 0.f);
#pragma unroll
    for (int k = 0; k < 8; k++) {
        float4 p = base[k * 512];
        acc.x += p.x; acc.y += p.y; acc.z += p.z; acc.w += p.w;
    }
    red[kseg][f] = acc;

    // ---- asum: 64 threads each grab one k-row (2 coalesced float4) ----
    if (tid < 64) {
        const float4* ap = (const float4*)&g_asum[(b * 64 + tid) * C_];
        float4 a0 = ap[0], a1 = ap[1];
        asred[tid][0] = a0.x; asred[tid][1] = a0.y;
        asred[tid][2] = a0.z; asred[tid][3] = a0.w;
        asred[tid][4] = a1.x; asred[tid][5] = a1.y;
        asred[tid][6] = a1.z; asred[tid][7] = a1.w;
    }
    __syncthreads();

    if (tid < C_) {
        float s = 0.0f;
#pragma unroll
        for (int k = 0; k < 64; k++) s += asred[k][tid];
        asumtot[tid] = s;
    }
    __syncthreads();

    // ---- final: 128 threads, thread = (c = tid>>4, dl = tid&15) ----
    if (tid < 128) {
        const int c  = tid >> 4;
        const int dl = tid & 15;
        const int fi = dl * 8 + c;        // float index within 128-float group
        float s = 0.0f;
#pragma unroll
        for (int seg = 0; seg < 8; seg++)
            s += ((const float*)&red[seg][fi >> 2])[fi & 3];
        const int d = dg * 16 + dl;
        out[b * (C_ * D_) + c * 256 + d] = s - asumtot[c] * centers[c * 256 + d];
    }
}

extern "C" void kernel_launch(void* const* d_in, const int* in_sizes, int n_in,
                              void* d_out, int out_size) {
    const float* x       = (const float*)d_in[0];
    const float* centers = (const float*)d_in[1];
    const float* scale   = (const float*)d_in[2];
    float* out           = (float*)d_out;
    (void)in_sizes; (void)n_in; (void)out_size;

    lde_main_kernel<<<NBLOCKS, NTHREADS>>>(x, centers, scale);
    lde_reduce_kernel<<<dim3(B_, 16), 256>>>(centers, out);
}

// round 13
// speedup vs baseline: 1.1664x; 1.0770x over previous
#include <cuda_runtime.h>
#include <cstdint>

#define B_ 16
#define T_ 2048
#define D_ 256
#define C_ 8
#define TILE 32
#define TPB 2                      // tiles per block
#define TCHUNK (TILE * TPB)        // 64 tokens per block
#define NCHUNKS (T_ / TCHUNK)      // 32
#define NBLOCKS (B_ * NCHUNKS)     // 512
#define NTHREADS 128
#define KPART NCHUNKS              // 32 partials per (b,d,c)

typedef unsigned long long ull;
union f4u { float4 v; ull u[2]; };

// scratch: per-block partial aggregates, layout [block][d][c]
__device__ float g_scratch[NBLOCKS * 2048];
__device__ float g_asum[NBLOCKS * C_];

__device__ __forceinline__ ull ffma2(ull a, ull b, ull c) {
    ull d;
    asm("fma.rn.f32x2 %0, %1, %2, %3;" : "=l"(d) : "l"(a), "l"(b), "l"(c));
    return d;
}
__device__ __forceinline__ float2 upk(ull v) {
    float2 r;
    asm("mov.b64 {%0, %1}, %2;" : "=f"(r.x), "=f"(r.y) : "l"(v));
    return r;
}
__device__ __forceinline__ ull pk2(float lo, float hi) {
    ull r;
    asm("mov.b64 %0, {%1, %2};" : "=l"(r) : "f"(lo), "f"(hi));
    return r;
}
__device__ __forceinline__ void cp16(uint32_t saddr, const void* g) {
    asm volatile("cp.async.cg.shared.global [%0], [%1], 16;" :: "r"(saddr), "l"(g));
}
#define CP_COMMIT() asm volatile("cp.async.commit_group;")
#define CP_WAIT0()  asm volatile("cp.async.wait_group 0;")

__global__ void __launch_bounds__(NTHREADS, 5) lde_main_kernel(
    const float* __restrict__ x,        // (B,T,D)
    const float* __restrict__ centers,  // (C,D)
    const float* __restrict__ scale)    // (C,)
{
    __shared__ float4 xbuf[TILE * 64];   // 32 KB, swizzled slot = d4 ^ t
    __shared__ float4 ct[64 * C_];       // 8 KB: [d4][c]
    __shared__ float  logit[TILE * 9];   // per token: 8 dots + xsq
    __shared__ float  a_s[TILE * C_];    // softmax weights
    __shared__ float  asum_s[C_];
    __shared__ float  csq_s[C_];
    __shared__ float  scl_s[C_];

    const int tid  = threadIdx.x;
    const int w    = tid >> 5;           // 0..3
    const int lane = tid & 31;
    const int b     = blockIdx.x >> 5;        // / NCHUNKS (32)
    const int chunk = blockIdx.x & (NCHUNKS - 1);

    const float4* gx4 = (const float4*)(x + ((size_t)b * T_ + chunk * TCHUNK) * D_);
    const uint32_t xs_base = (uint32_t)__cvta_generic_to_shared(xbuf);

    // ---- issue tile 0 load (32 KB) ----
#pragma unroll
    for (int j = 0; j < 16; j++) {
        int i = tid + j * NTHREADS;
        int t = i >> 6, d4 = i & 63;
        cp16(xs_base + (uint32_t)((t * 64 + (d4 ^ t)) * 16), gx4 + i);
    }
    CP_COMMIT();

    // ---- init (overlaps cp.async flight) ----
    for (int i = tid; i < TILE * 9; i += NTHREADS) logit[i] = 0.0f;
    if (tid < C_) { asum_s[tid] = 0.0f; scl_s[tid] = scale[tid]; }
    for (int i = tid; i < C_ * D_; i += NTHREADS) {
        int c = i >> 8, d = i & 255;
        ((float*)ct)[((d >> 2) * C_ + c) * 4 + (d & 3)] = centers[i];
    }
    {
        float s0 = 0.0f, s1 = 0.0f;
#pragma unroll
        for (int j = 0; j < 8; j++) {
            float v0 = centers[(2 * w) * D_ + lane + 32 * j];
            float v1 = centers[(2 * w + 1) * D_ + lane + 32 * j];
            s0 = fmaf(v0, v0, s0);
            s1 = fmaf(v1, v1, s1);
        }
#pragma unroll
        for (int o = 16; o; o >>= 1) {
            s0 += __shfl_xor_sync(0xffffffffu, s0, o);
            s1 += __shfl_xor_sync(0xffffffffu, s1, o);
        }
        if (lane == 0) { csq_s[2 * w] = s0; csq_s[2 * w + 1] = s1; }
    }

    // phase-B constants and cross-tile accumulators
    const int d4l = tid >> 1;
    const int off = (tid & 1) * 2;
    ull acc2[8];
#pragma unroll
    for (int j = 0; j < 8; j++) acc2[j] = 0ULL;

#pragma unroll
    for (int tile = 0; tile < TPB; tile++) {
        CP_WAIT0();
        __syncthreads();   // tile data + (logit zeroed) ready

        // ---- phase A: lane = token, warp w covers d4 in [16w, 16w+16) ----
        {
            ull red[9];
#pragma unroll
            for (int j = 0; j < 9; j++) red[j] = 0ULL;
#pragma unroll
            for (int i = 0; i < 16; i++) {
                const int d4 = w * 16 + i;
                f4u xv; xv.v = xbuf[lane * 64 + (d4 ^ lane)];
#pragma unroll
                for (int c = 0; c < C_; c++) {
                    f4u cv; cv.v = ct[d4 * C_ + c];
                    red[c] = ffma2(xv.u[0], cv.u[0], ffma2(xv.u[1], cv.u[1], red[c]));
                }
                red[8] = ffma2(xv.u[0], xv.u[0], ffma2(xv.u[1], xv.u[1], red[8]));
            }
#pragma unroll
            for (int j = 0; j < 9; j++) {
                float2 p = upk(red[j]);
                atomicAdd(&logit[lane * 9 + j], p.x + p.y);
            }
        }
        __syncthreads();

        // ---- softmax: thread = (t = tid/4, cluster pair q = tid%4) ----
        // reads logit, then zeroes its entries for the next tile (same-warp safe)
        {
            const int t  = tid >> 2;
            const int q  = tid & 3;
            const int c0 = 2 * q, c1 = 2 * q + 1;
            const float dot0 = logit[t * 9 + c0];
            const float dot1 = logit[t * 9 + c1];
            const float xsq  = logit[t * 9 + 8];
            logit[t * 9 + c0] = 0.0f;
            logit[t * 9 + c1] = 0.0f;
            if (q == 0) logit[t * 9 + 8] = 0.0f;
            float lg0 = scl_s[c0] * (2.0f * dot0 - xsq - csq_s[c0]);
            float lg1 = scl_s[c1] * (2.0f * dot1 - xsq - csq_s[c1]);
            float m = fmaxf(lg0, lg1);
            m = fmaxf(m, __shfl_xor_sync(0xffffffffu, m, 1));
            m = fmaxf(m, __shfl_xor_sync(0xffffffffu, m, 2));
            const float e0 = __expf(lg0 - m);
            const float e1 = __expf(lg1 - m);
            float sd = e0 + e1;
            sd += __shfl_xor_sync(0xffffffffu, sd, 1);
            sd += __shfl_xor_sync(0xffffffffu, sd, 2);
            const float inv = 1.0f / sd;
            const float a0 = e0 * inv, a1 = e1 * inv;
            *(float2*)&a_s[t * 8 + c0] = make_float2(a0, a1);
            float r0 = a0, r1 = a1;
            r0 += __shfl_xor_sync(0xffffffffu, r0, 4);
            r1 += __shfl_xor_sync(0xffffffffu, r1, 4);
            r0 += __shfl_xor_sync(0xffffffffu, r0, 8);
            r1 += __shfl_xor_sync(0xffffffffu, r1, 8);
            r0 += __shfl_xor_sync(0xffffffffu, r0, 16);
            r1 += __shfl_xor_sync(0xffffffffu, r1, 16);
            if (lane < 4) {
                atomicAdd(&asum_s[c0], r0);
                atomicAdd(&asum_s[c1], r1);
            }
        }
        __syncthreads();

        // ---- phase B: thread owns dims {2*tid, 2*tid+1}, accumulate tile ----
        {
            const float* xbf = (const float*)xbuf;
#pragma unroll 4
            for (int t = 0; t < TILE; t++) {
                const ull xp = *(const ull*)(xbf + (t * 64 + (d4l ^ t)) * 4 + off);
                const float2 xv = upk(xp);
                const ull xd0 = pk2(xv.x, xv.x);
                const ull xd1 = pk2(xv.y, xv.y);
                f4u a0; a0.v = *(const float4*)&a_s[t * 8];
                f4u a1; a1.v = *(const float4*)&a_s[t * 8 + 4];
                acc2[0] = ffma2(a0.u[0], xd0, acc2[0]);
                acc2[1] = ffma2(a0.u[0], xd1, acc2[1]);
                acc2[2] = ffma2(a0.u[1], xd0, acc2[2]);
                acc2[3] = ffma2(a0.u[1], xd1, acc2[3]);
                acc2[4] = ffma2(a1.u[0], xd0, acc2[4]);
                acc2[5] = ffma2(a1.u[0], xd1, acc2[5]);
                acc2[6] = ffma2(a1.u[1], xd0, acc2[6]);
                acc2[7] = ffma2(a1.u[1], xd1, acc2[7]);
            }
        }

        // ---- issue next tile load after xbuf reads complete ----
        if (tile + 1 < TPB) {
            __syncthreads();
            const float4* src = gx4 + (tile + 1) * (TILE * 64);
#pragma unroll
            for (int j = 0; j < 16; j++) {
                int i = tid + j * NTHREADS;
                int t = i >> 6, d4 = i & 63;
                cp16(xs_base + (uint32_t)((t * 64 + (d4 ^ t)) * 16), src + i);
            }
            CP_COMMIT();
        }
    }

    // ---- epilogue: vectorized stores of raw partials ----
    {
        float* sb = g_scratch + (size_t)blockIdx.x * 2048;   // [d][c]
        const int d0 = 2 * tid, d1 = 2 * tid + 1;
        f4u q0, q1, q2, q3;
        q0.u[0] = acc2[0]; q0.u[1] = acc2[2];
        q1.u[0] = acc2[4]; q1.u[1] = acc2[6];
        q2.u[0] = acc2[1]; q2.u[1] = acc2[3];
        q3.u[0] = acc2[5]; q3.u[1] = acc2[7];
        *(float4*)(sb + d0 * 8)     = q0.v;
        *(float4*)(sb + d0 * 8 + 4) = q1.v;
        *(float4*)(sb + d1 * 8)     = q2.v;
        *(float4*)(sb + d1 * 8 + 4) = q3.v;
        if (tid < C_) g_asum[blockIdx.x * C_ + tid] = asum_s[tid];
    }
}

// stage 2: block (b, dg) reduces KPART=32 partials for a 16-d group.
__global__ void __launch_bounds__(256) lde_reduce_kernel(
    const float* __restrict__ centers,
    float* __restrict__ out)
{
    const int b    = blockIdx.x;          // 16
    const int dg   = blockIdx.y;          // 16 groups of 16 d-values
    const int tid  = threadIdx.x;
    const int f    = tid & 31;            // float4 index within 128-float group
    const int kseg = tid >> 5;            // 0..7 (4 k per segment)

    __shared__ float4 red[8][32];
    __shared__ float  asred[KPART][8];
    __shared__ float  asumtot[C_];

    const float4* base = (const float4*)g_scratch
                       + ((size_t)(b * KPART + kseg * 4)) * 512 + dg * 32 + f;
    float4 acc = make_float4(0.f, 0.f, 0.f, 0.f);
#pragma unroll
    for (int k = 0; k < 4; k++) {
        float4 p = base[k * 512];
        acc.x += p.x; acc.y += p.y; acc.z += p.z; acc.w += p.w;
    }
    red[kseg][f] = acc;

    if (tid < KPART) {
        const float4* ap = (const float4*)&g_asum[(b * KPART + tid) * C_];
        float4 a0 = ap[0], a1 = ap[1];
        asred[tid][0] = a0.x; asred[tid][1] = a0.y;
        asred[tid][2] = a0.z; asred[tid][3] = a0.w;
        asred[tid][4] = a1.x; asred[tid][5] = a1.y;
        asred[tid][6] = a1.z; asred[tid][7] = a1.w;
    }
    __syncthreads();

    if (tid < C_) {
        float s = 0.0f;
#pragma unroll
        for (int k = 0; k < KPART; k++) s += asred[k][tid];
        asumtot[tid] = s;
    }
    __syncthreads();

    if (tid < 128) {
        const int c  = tid >> 4;
        const int dl = tid & 15;
        const int fi = dl * 8 + c;
        float s = 0.0f;
#pragma unroll
        for (int seg = 0; seg < 8; seg++)
            s += ((const float*)&red[seg][fi >> 2])[fi & 3];
        const int d = dg * 16 + dl;
        out[b * (C_ * D_) + c * 256 + d] = s - asumtot[c] * centers[c * 256 + d];
    }
}

extern "C" void kernel_launch(void* const* d_in, const int* in_sizes, int n_in,
                              void* d_out, int out_size) {
    const float* x       = (const float*)d_in[0];
    const float* centers = (const float*)d_in[1];
    const float* scale   = (const float*)d_in[2];
    float* out           = (float*)d_out;
    (void)in_sizes; (void)n_in; (void)out_size;

    lde_main_kernel<<<NBLOCKS, NTHREADS>>>(x, centers, scale);
    lde_reduce_kernel<<<dim3(B_, 16), 256>>>(centers, out);
}